// round 1
// baseline (speedup 1.0000x reference)
#include <cuda_runtime.h>
#include <math.h>

#define D 64
#define MAXN 100000

// ---------------- static device scratch (no allocations allowed) ----------------
__device__ float g_x  [MAXN * D];   // x_in = concat(u, v)
__device__ float g_x2 [MAXN * D];   // relu(BN(stage1)) output
__device__ float g_xui[MAXN * D];
__device__ float g_xvi[MAXN * D];
__device__ float g_xvj[MAXN * D];   // includes +bv
__device__ float g_y  [MAXN * D];   // stage output accumulator (x@Uj + bu + agg)
__device__ float g_stats1[2 * D];   // col sums, col sumsq
__device__ float g_stats2[2 * D];

#define FMA4(ACC, A, B) do { (ACC).x += (A)*(B).x; (ACC).y += (A)*(B).y; \
                             (ACC).z += (A)*(B).z; (ACC).w += (A)*(B).w; } while(0)

// ---------------- fused 4-matrix GEMM: X[64-row tile] @ [Ui|Uj|Vi|Vj] ----------------
// block: 256 threads (16 tx x 16 ty); thread tile: 4 rows x 16 cols
// dyn smem: Ws [64][256] (64KB) + Xs [64][68] (17KB)
#define XS_STRIDE 68
#define GEMM4_SMEM (64*256*4 + 64*XS_STRIDE*4)

__global__ void gemm4_kernel(const float* __restrict__ X,
                             const float* __restrict__ Ui, const float* __restrict__ Uj,
                             const float* __restrict__ Vi, const float* __restrict__ Vj,
                             const float* __restrict__ bu, const float* __restrict__ bv,
                             float* __restrict__ xui, float* __restrict__ y,
                             float* __restrict__ xvi, float* __restrict__ xvj,
                             int n)
{
    extern __shared__ float smem[];
    float* Ws = smem;              // [64][256]
    float* Xs = smem + 64 * 256;   // [64][XS_STRIDE]
    const int tid = threadIdx.x;
    const int rowBase = blockIdx.x * 64;

    // stage W (4 matrices side by side) and X tile into smem
    {
        const float* mats[4] = {Ui, Uj, Vi, Vj};
        #pragma unroll
        for (int m = 0; m < 4; m++) {
            const float4* src = (const float4*)mats[m];
            for (int i = tid; i < 1024; i += 256) {
                int k = i >> 4, j4 = i & 15;
                ((float4*)(Ws + k * 256 + m * 64))[j4] = src[k * 16 + j4];
            }
        }
        for (int i = tid; i < 1024; i += 256) {
            int r = i >> 4, c4 = i & 15;
            int row = rowBase + r;
            float4 v = make_float4(0.f, 0.f, 0.f, 0.f);
            if (row < n) v = ((const float4*)X)[row * 16 + c4];
            *(float4*)(Xs + r * XS_STRIDE + c4 * 4) = v;
        }
    }
    __syncthreads();

    const int tx = tid & 15;
    const int ty = tid >> 4;
    float4 acc[4][4];
    #pragma unroll
    for (int r = 0; r < 4; r++)
        #pragma unroll
        for (int c = 0; c < 4; c++) acc[r][c] = make_float4(0.f, 0.f, 0.f, 0.f);

    #pragma unroll 8
    for (int k = 0; k < 64; k++) {
        float a0 = Xs[(ty * 4 + 0) * XS_STRIDE + k];
        float a1 = Xs[(ty * 4 + 1) * XS_STRIDE + k];
        float a2 = Xs[(ty * 4 + 2) * XS_STRIDE + k];
        float a3 = Xs[(ty * 4 + 3) * XS_STRIDE + k];
        const float4* wrow = (const float4*)(Ws + k * 256);
        float4 b0 = wrow[tx * 4 + 0];
        float4 b1 = wrow[tx * 4 + 1];
        float4 b2 = wrow[tx * 4 + 2];
        float4 b3 = wrow[tx * 4 + 3];
        FMA4(acc[0][0], a0, b0); FMA4(acc[0][1], a0, b1); FMA4(acc[0][2], a0, b2); FMA4(acc[0][3], a0, b3);
        FMA4(acc[1][0], a1, b0); FMA4(acc[1][1], a1, b1); FMA4(acc[1][2], a1, b2); FMA4(acc[1][3], a1, b3);
        FMA4(acc[2][0], a2, b0); FMA4(acc[2][1], a2, b1); FMA4(acc[2][2], a2, b2); FMA4(acc[2][3], a2, b3);
        FMA4(acc[3][0], a3, b0); FMA4(acc[3][1], a3, b1); FMA4(acc[3][2], a3, b2); FMA4(acc[3][3], a3, b3);
    }

    // this thread's 16 cols all belong to one matrix
    const int m = tx >> 2;               // 0:Ui 1:Uj 2:Vi 3:Vj
    const int ccb = (tx & 3) * 16;       // col base within matrix
    float* dst; const float* bias;
    if      (m == 0) { dst = xui; bias = nullptr; }
    else if (m == 1) { dst = y;   bias = bu; }
    else if (m == 2) { dst = xvi; bias = nullptr; }
    else             { dst = xvj; bias = bv; }

    float4 bb[4];
    #pragma unroll
    for (int c = 0; c < 4; c++) {
        if (bias) bb[c] = ((const float4*)bias)[(ccb >> 2) + c];
        else      bb[c] = make_float4(0.f, 0.f, 0.f, 0.f);
    }

    #pragma unroll
    for (int r = 0; r < 4; r++) {
        int row = rowBase + ty * 4 + r;
        if (row < n) {
            float4* o = (float4*)(dst + row * 64 + ccb);
            #pragma unroll
            for (int c = 0; c < 4; c++) {
                float4 v = acc[r][c];
                v.x += bb[c].x; v.y += bb[c].y; v.z += bb[c].z; v.w += bb[c].w;
                o[c] = v;
            }
        }
    }
}

// ---------------- edge kernel: 16 threads per edge ----------------
__global__ void edge_kernel(const int* __restrict__ es, const int* __restrict__ ee,
                            const float* __restrict__ xvi, const float* __restrict__ xvj,
                            const float* __restrict__ xui, float* __restrict__ y, int nE)
{
    int t = blockIdx.x * blockDim.x + threadIdx.x;
    int e = t >> 4;
    int lane = t & 15;
    if (e >= nE) return;
    int a = __ldg(ee + e);   // destination (gather xVi, scatter)
    int b = __ldg(es + e);   // source
    float4 vi = __ldg((const float4*)(xvi + (size_t)a * 64) + lane);
    float4 vj = __ldg((const float4*)(xvj + (size_t)b * 64) + lane);  // includes bv
    float4 ui = __ldg((const float4*)(xui + (size_t)b * 64) + lane);
    float4 g;
    g.x = 1.f / (1.f + __expf(-(vi.x + vj.x)));
    g.y = 1.f / (1.f + __expf(-(vi.y + vj.y)));
    g.z = 1.f / (1.f + __expf(-(vi.z + vj.z)));
    g.w = 1.f / (1.f + __expf(-(vi.w + vj.w)));
    float* yp = y + (size_t)a * 64 + lane * 4;
    atomicAdd(yp + 0, g.x * ui.x);
    atomicAdd(yp + 1, g.y * ui.y);
    atomicAdd(yp + 2, g.z * ui.z);
    atomicAdd(yp + 3, g.w * ui.w);
}

// ---------------- batchnorm stats: per-column sum / sumsq ----------------
__global__ void bn_stats_kernel(const float* __restrict__ x, float* __restrict__ stats, int n)
{
    int col = threadIdx.x & 63;
    int rl  = threadIdx.x >> 6;    // 0..3
    float s = 0.f, s2 = 0.f;
    for (int r = blockIdx.x * 4 + rl; r < n; r += gridDim.x * 4) {
        float v = x[(size_t)r * 64 + col];
        s += v; s2 += v * v;
    }
    __shared__ float sh[256], sh2[256];
    sh[threadIdx.x] = s; sh2[threadIdx.x] = s2;
    __syncthreads();
    if (rl == 0) {
        s  = sh[col]  + sh[col + 64]  + sh[col + 128]  + sh[col + 192];
        s2 = sh2[col] + sh2[col + 64] + sh2[col + 128] + sh2[col + 192];
        atomicAdd(stats + col, s);
        atomicAdd(stats + 64 + col, s2);
    }
}

// ---------------- BN + ReLU apply ----------------
__global__ void bn_apply_relu_kernel(const float* __restrict__ x, const float* __restrict__ stats,
                                     const float* __restrict__ gamma, const float* __restrict__ beta,
                                     float* __restrict__ out, int n)
{
    int i = blockIdx.x * blockDim.x + threadIdx.x;   // float4 index
    int total = n * 16;
    if (i >= total) return;
    int c4 = i & 15;
    float fn = 1.f / (float)n;
    float4 v = ((const float4*)x)[i];
    float r[4] = {v.x, v.y, v.z, v.w};
    #pragma unroll
    for (int j = 0; j < 4; j++) {
        int c = c4 * 4 + j;
        float mean = stats[c] * fn;
        float var  = stats[64 + c] * fn - mean * mean;
        float scale = gamma[c] * rsqrtf(var + 1e-3f);
        float val = scale * (r[j] - mean) + beta[c];
        r[j] = val > 0.f ? val : 0.f;
    }
    ((float4*)out)[i] = make_float4(r[0], r[1], r[2], r[3]);
}

// ---------------- final: out = relu( BN2(y2) + x_in @ R ) ----------------
__global__ void final_kernel(const float* __restrict__ X, const float* __restrict__ R,
                             const float* __restrict__ y2, const float* __restrict__ stats,
                             const float* __restrict__ gamma, const float* __restrict__ beta,
                             float* __restrict__ out, int n)
{
    __shared__ float Rs[64 * 64];
    __shared__ float Xs[64 * XS_STRIDE];
    const int tid = threadIdx.x;
    const int rowBase = blockIdx.x * 64;

    for (int i = tid; i < 1024; i += 256)
        ((float4*)Rs)[i] = ((const float4*)R)[i];
    for (int i = tid; i < 1024; i += 256) {
        int r = i >> 4, c4 = i & 15;
        int row = rowBase + r;
        float4 v = make_float4(0.f, 0.f, 0.f, 0.f);
        if (row < n) v = ((const float4*)X)[row * 16 + c4];
        *(float4*)(Xs + r * XS_STRIDE + c4 * 4) = v;
    }
    __syncthreads();

    const int tx = tid & 15;   // cols tx*4 .. tx*4+3
    const int ty = tid >> 4;   // rows ty*4 .. ty*4+3
    float4 acc[4];
    #pragma unroll
    for (int r = 0; r < 4; r++) acc[r] = make_float4(0.f, 0.f, 0.f, 0.f);

    #pragma unroll 8
    for (int k = 0; k < 64; k++) {
        float a0 = Xs[(ty * 4 + 0) * XS_STRIDE + k];
        float a1 = Xs[(ty * 4 + 1) * XS_STRIDE + k];
        float a2 = Xs[(ty * 4 + 2) * XS_STRIDE + k];
        float a3 = Xs[(ty * 4 + 3) * XS_STRIDE + k];
        float4 b = ((const float4*)(Rs + k * 64))[tx];
        FMA4(acc[0], a0, b);
        FMA4(acc[1], a1, b);
        FMA4(acc[2], a2, b);
        FMA4(acc[3], a3, b);
    }

    // per-column BN coefficients
    float fn = 1.f / (float)n;
    float scale[4], shift[4];
    #pragma unroll
    for (int j = 0; j < 4; j++) {
        int c = tx * 4 + j;
        float mean = stats[c] * fn;
        float var  = stats[64 + c] * fn - mean * mean;
        float sc = gamma[c] * rsqrtf(var + 1e-3f);
        scale[j] = sc;
        shift[j] = beta[c] - mean * sc;
    }

    #pragma unroll
    for (int r = 0; r < 4; r++) {
        int row = rowBase + ty * 4 + r;
        if (row < n) {
            float4 yv = ((const float4*)(y2 + (size_t)row * 64))[tx];
            float o0 = acc[r].x + yv.x * scale[0] + shift[0];
            float o1 = acc[r].y + yv.y * scale[1] + shift[1];
            float o2 = acc[r].z + yv.z * scale[2] + shift[2];
            float o3 = acc[r].w + yv.w * scale[3] + shift[3];
            float4 ov;
            ov.x = o0 > 0.f ? o0 : 0.f;
            ov.y = o1 > 0.f ? o1 : 0.f;
            ov.z = o2 > 0.f ? o2 : 0.f;
            ov.w = o3 > 0.f ? o3 : 0.f;
            ((float4*)(out + (size_t)row * 64))[tx] = ov;
        }
    }
}

__global__ void zero_stats_kernel()
{
    int t = threadIdx.x;
    if (t < 128) g_stats1[t] = 0.f;
    else         g_stats2[t - 128] = 0.f;
}

// ---------------- host ----------------
extern "C" void kernel_launch(void* const* d_in, const int* in_sizes, int n_in,
                              void* d_out, int out_size)
{
    const float* u   = (const float*)d_in[0];
    const float* v   = (const float*)d_in[1];
    const int*   es  = (const int*)  d_in[2];
    const int*   ee  = (const int*)  d_in[3];
    const float* Ui1 = (const float*)d_in[4];
    const float* Uj1 = (const float*)d_in[5];
    const float* Vi1 = (const float*)d_in[6];
    const float* Vj1 = (const float*)d_in[7];
    const float* bu1 = (const float*)d_in[8];
    const float* bv1 = (const float*)d_in[9];
    const float* Ui2 = (const float*)d_in[10];
    const float* Uj2 = (const float*)d_in[11];
    const float* Vi2 = (const float*)d_in[12];
    const float* Vj2 = (const float*)d_in[13];
    const float* bu2 = (const float*)d_in[14];
    const float* bv2 = (const float*)d_in[15];
    const float* R   = (const float*)d_in[16];
    const float* gamma1 = (const float*)d_in[17];
    const float* beta1  = (const float*)d_in[18];
    const float* gamma2 = (const float*)d_in[19];
    const float* beta2  = (const float*)d_in[20];

    const int nU = in_sizes[0] / 64;
    const int nV = in_sizes[1] / 64;
    const int n  = nU + nV;
    const int nE = in_sizes[2];

    float *px, *px2, *pxui, *pxvi, *pxvj, *py, *pst1, *pst2;
    cudaGetSymbolAddress((void**)&px,   g_x);
    cudaGetSymbolAddress((void**)&px2,  g_x2);
    cudaGetSymbolAddress((void**)&pxui, g_xui);
    cudaGetSymbolAddress((void**)&pxvi, g_xvi);
    cudaGetSymbolAddress((void**)&pxvj, g_xvj);
    cudaGetSymbolAddress((void**)&py,   g_y);
    cudaGetSymbolAddress((void**)&pst1, g_stats1);
    cudaGetSymbolAddress((void**)&pst2, g_stats2);

    cudaFuncSetAttribute(gemm4_kernel, cudaFuncAttributeMaxDynamicSharedMemorySize, GEMM4_SMEM);

    // x_in = concat(u, v)
    cudaMemcpyAsync(px,                u, (size_t)nU * 64 * sizeof(float), cudaMemcpyDeviceToDevice);
    cudaMemcpyAsync(px + (size_t)nU * 64, v, (size_t)nV * 64 * sizeof(float), cudaMemcpyDeviceToDevice);

    zero_stats_kernel<<<1, 256>>>();

    const int gemmBlocks = (n + 63) / 64;
    const int edgeBlocks = (nE * 16 + 255) / 256;

    // stage 1
    gemm4_kernel<<<gemmBlocks, 256, GEMM4_SMEM>>>(px, Ui1, Uj1, Vi1, Vj1, bu1, bv1,
                                                  pxui, py, pxvi, pxvj, n);
    edge_kernel<<<edgeBlocks, 256>>>(es, ee, pxvi, pxvj, pxui, py, nE);
    bn_stats_kernel<<<1024, 256>>>(py, pst1, n);
    bn_apply_relu_kernel<<<(n * 16 + 255) / 256, 256>>>(py, pst1, gamma1, beta1, px2, n);

    // stage 2
    gemm4_kernel<<<gemmBlocks, 256, GEMM4_SMEM>>>(px2, Ui2, Uj2, Vi2, Vj2, bu2, bv2,
                                                  pxui, py, pxvi, pxvj, n);
    edge_kernel<<<edgeBlocks, 256>>>(es, ee, pxvi, pxvj, pxui, py, nE);
    bn_stats_kernel<<<1024, 256>>>(py, pst2, n);

    // final: relu(BN2(y) + x_in @ R)
    final_kernel<<<gemmBlocks, 256>>>(px, R, py, pst2, gamma2, beta2, (float*)d_out, n);
}

// round 2
// speedup vs baseline: 1.0597x; 1.0597x over previous
#include <cuda_runtime.h>
#include <math.h>

#define D 64
#define MAXN 100000
#define MAXE 1100000
#define NCHUNK 1024

// ---------------- static device scratch ----------------
__device__ float g_x  [MAXN * D];   // x_in = concat(u, v)
__device__ float g_xui[MAXN * D];
__device__ float g_xvi[MAXN * D];
__device__ float g_xvj[MAXN * D];   // includes +bv
__device__ float g_y  [MAXN * D];   // stage1 output
__device__ float g_y2 [MAXN * D];   // stage2 output
__device__ float g_stats1[2 * D];
__device__ float g_stats2[2 * D];
// CSR (edges sorted by destination)
__device__ int g_cnt[MAXN + 1];
__device__ int g_off[MAXN + 1];
__device__ int g_cur[MAXN];
__device__ int g_srcSorted[MAXE];
__device__ int g_bsum[NCHUNK];

#define FMA4(ACC, A, B) do { (ACC).x += (A)*(B).x; (ACC).y += (A)*(B).y; \
                             (ACC).z += (A)*(B).z; (ACC).w += (A)*(B).w; } while(0)

// ================= CSR build =================
__global__ void hist_kernel(const int* __restrict__ ee, int nE)
{
    int e = blockIdx.x * blockDim.x + threadIdx.x;
    if (e < nE) atomicAdd(&g_cnt[ee[e]], 1);
}

__global__ void scanA_kernel(int n, int C)
{
    int t = blockIdx.x * blockDim.x + threadIdx.x;  // 0..NCHUNK-1
    int base = t * C, s = 0;
    for (int i = 0; i < C; i++) {
        int idx = base + i;
        if (idx < n) s += g_cnt[idx];
    }
    g_bsum[t] = s;
}

__global__ void scanB_kernel()
{
    __shared__ int sh[NCHUNK];
    int t = threadIdx.x;
    int v = g_bsum[t];
    sh[t] = v;
    __syncthreads();
    #pragma unroll
    for (int ofs = 1; ofs < NCHUNK; ofs <<= 1) {
        int x = (t >= ofs) ? sh[t - ofs] : 0;
        __syncthreads();
        sh[t] += x;
        __syncthreads();
    }
    g_bsum[t] = sh[t] - v;   // exclusive
}

__global__ void scanC_kernel(int n, int C)
{
    int t = blockIdx.x * blockDim.x + threadIdx.x;
    int base = t * C;
    int run = g_bsum[t];
    for (int i = 0; i < C; i++) {
        int idx = base + i;
        if (idx < n) {
            g_off[idx] = run;
            g_cur[idx] = run;
            run += g_cnt[idx];
        }
    }
    if (t == NCHUNK - 1) g_off[n] = run;
}

__global__ void scatter_kernel(const int* __restrict__ es, const int* __restrict__ ee, int nE)
{
    int e = blockIdx.x * blockDim.x + threadIdx.x;
    if (e < nE) {
        int d = ee[e];
        int p = atomicAdd(&g_cur[d], 1);
        g_srcSorted[p] = es[e];
    }
}

// ================= fused 4-matrix GEMM: X @ [Ui|Uj|Vi|Vj] =================
// optional fused input transform: x' = relu(gamma*(x-mean)*rsqrt(var+eps)+beta)
#define XS_STRIDE 68
#define GEMM4_SMEM (64*256*4 + 64*XS_STRIDE*4)

template<bool BN>
__global__ void gemm4_kernel(const float* __restrict__ X,
                             const float* __restrict__ Ui, const float* __restrict__ Uj,
                             const float* __restrict__ Vi, const float* __restrict__ Vj,
                             const float* __restrict__ bu, const float* __restrict__ bv,
                             const float* __restrict__ stats, const float* __restrict__ gamma,
                             const float* __restrict__ beta,
                             float* __restrict__ xui, float* __restrict__ y,
                             float* __restrict__ xvi, float* __restrict__ xvj,
                             int n)
{
    extern __shared__ float smem[];
    float* Ws = smem;              // [64][256]
    float* Xs = smem + 64 * 256;   // [64][XS_STRIDE]
    __shared__ float s_scale[64], s_shift[64];
    const int tid = threadIdx.x;
    const int rowBase = blockIdx.x * 64;

    if (BN) {
        if (tid < 64) {
            float fn = 1.f / (float)n;
            float mean = stats[tid] * fn;
            float var  = stats[64 + tid] * fn - mean * mean;
            float sc = gamma[tid] * rsqrtf(var + 1e-3f);
            s_scale[tid] = sc;
            s_shift[tid] = beta[tid] - mean * sc;
        }
        __syncthreads();
    }

    {
        const float* mats[4] = {Ui, Uj, Vi, Vj};
        #pragma unroll
        for (int m = 0; m < 4; m++) {
            const float4* src = (const float4*)mats[m];
            for (int i = tid; i < 1024; i += 256) {
                int k = i >> 4, j4 = i & 15;
                ((float4*)(Ws + k * 256 + m * 64))[j4] = src[k * 16 + j4];
            }
        }
        for (int i = tid; i < 1024; i += 256) {
            int r = i >> 4, c4 = i & 15;
            int row = rowBase + r;
            float4 v = make_float4(0.f, 0.f, 0.f, 0.f);
            if (row < n) v = ((const float4*)X)[row * 16 + c4];
            if (BN) {
                int c = c4 * 4;
                v.x = fmaxf(v.x * s_scale[c+0] + s_shift[c+0], 0.f);
                v.y = fmaxf(v.y * s_scale[c+1] + s_shift[c+1], 0.f);
                v.z = fmaxf(v.z * s_scale[c+2] + s_shift[c+2], 0.f);
                v.w = fmaxf(v.w * s_scale[c+3] + s_shift[c+3], 0.f);
            }
            *(float4*)(Xs + r * XS_STRIDE + c4 * 4) = v;
        }
    }
    __syncthreads();

    const int tx = tid & 15;
    const int ty = tid >> 4;
    float4 acc[4][4];
    #pragma unroll
    for (int r = 0; r < 4; r++)
        #pragma unroll
        for (int c = 0; c < 4; c++) acc[r][c] = make_float4(0.f, 0.f, 0.f, 0.f);

    #pragma unroll 8
    for (int k = 0; k < 64; k++) {
        float a0 = Xs[(ty * 4 + 0) * XS_STRIDE + k];
        float a1 = Xs[(ty * 4 + 1) * XS_STRIDE + k];
        float a2 = Xs[(ty * 4 + 2) * XS_STRIDE + k];
        float a3 = Xs[(ty * 4 + 3) * XS_STRIDE + k];
        const float4* wrow = (const float4*)(Ws + k * 256);
        float4 b0 = wrow[tx * 4 + 0];
        float4 b1 = wrow[tx * 4 + 1];
        float4 b2 = wrow[tx * 4 + 2];
        float4 b3 = wrow[tx * 4 + 3];
        FMA4(acc[0][0], a0, b0); FMA4(acc[0][1], a0, b1); FMA4(acc[0][2], a0, b2); FMA4(acc[0][3], a0, b3);
        FMA4(acc[1][0], a1, b0); FMA4(acc[1][1], a1, b1); FMA4(acc[1][2], a1, b2); FMA4(acc[1][3], a1, b3);
        FMA4(acc[2][0], a2, b0); FMA4(acc[2][1], a2, b1); FMA4(acc[2][2], a2, b2); FMA4(acc[2][3], a2, b3);
        FMA4(acc[3][0], a3, b0); FMA4(acc[3][1], a3, b1); FMA4(acc[3][2], a3, b2); FMA4(acc[3][3], a3, b3);
    }

    const int m = tx >> 2;
    const int ccb = (tx & 3) * 16;
    float* dst; const float* bias;
    if      (m == 0) { dst = xui; bias = nullptr; }
    else if (m == 1) { dst = y;   bias = bu; }
    else if (m == 2) { dst = xvi; bias = nullptr; }
    else             { dst = xvj; bias = bv; }

    float4 bb[4];
    #pragma unroll
    for (int c = 0; c < 4; c++) {
        if (bias) bb[c] = ((const float4*)bias)[(ccb >> 2) + c];
        else      bb[c] = make_float4(0.f, 0.f, 0.f, 0.f);
    }

    #pragma unroll
    for (int r = 0; r < 4; r++) {
        int row = rowBase + ty * 4 + r;
        if (row < n) {
            float4* o = (float4*)(dst + row * 64 + ccb);
            #pragma unroll
            for (int c = 0; c < 4; c++) {
                float4 v = acc[r][c];
                v.x += bb[c].x; v.y += bb[c].y; v.z += bb[c].z; v.w += bb[c].w;
                o[c] = v;
            }
        }
    }
}

// ================= per-node aggregation (CSR, no atomics) + fused BN stats =================
// 16 threads per node, 16 nodes per 256-thread block
__global__ void agg_kernel(const float* __restrict__ xvi, const float* __restrict__ xvj,
                           const float* __restrict__ xui, float* __restrict__ y,
                           float* __restrict__ stats, int n)
{
    __shared__ float s_sum[64], s_sum2[64];
    const int tid = threadIdx.x;
    if (tid < 64) { s_sum[tid] = 0.f; s_sum2[tid] = 0.f; }
    __syncthreads();

    const int lane = tid & 15;
    const int grp  = tid >> 4;
    const int node = blockIdx.x * 16 + grp;

    if (node < n) {
        float4 vi  = ((const float4*)(xvi + (size_t)node * 64))[lane];
        float4 acc = ((const float4*)(y   + (size_t)node * 64))[lane];  // x@Uj + bu
        int p0 = g_off[node];
        int p1 = g_off[node + 1];
        for (int p = p0; p < p1; p++) {
            int b = g_srcSorted[p];
            float4 vj = __ldg((const float4*)(xvj + (size_t)b * 64) + lane);
            float4 ui = __ldg((const float4*)(xui + (size_t)b * 64) + lane);
            acc.x += ui.x / (1.f + __expf(-(vi.x + vj.x)));
            acc.y += ui.y / (1.f + __expf(-(vi.y + vj.y)));
            acc.z += ui.z / (1.f + __expf(-(vi.z + vj.z)));
            acc.w += ui.w / (1.f + __expf(-(vi.w + vj.w)));
        }
        ((float4*)(y + (size_t)node * 64))[lane] = acc;

        int c = lane * 4;
        atomicAdd(&s_sum[c + 0], acc.x);  atomicAdd(&s_sum2[c + 0], acc.x * acc.x);
        atomicAdd(&s_sum[c + 1], acc.y);  atomicAdd(&s_sum2[c + 1], acc.y * acc.y);
        atomicAdd(&s_sum[c + 2], acc.z);  atomicAdd(&s_sum2[c + 2], acc.z * acc.z);
        atomicAdd(&s_sum[c + 3], acc.w);  atomicAdd(&s_sum2[c + 3], acc.w * acc.w);
    }
    __syncthreads();
    if (tid < 64) {
        atomicAdd(stats + tid,      s_sum[tid]);
        atomicAdd(stats + 64 + tid, s_sum2[tid]);
    }
}

// ================= final: out = relu( BN2(y2) + x_in @ R ) =================
__global__ void final_kernel(const float* __restrict__ X, const float* __restrict__ R,
                             const float* __restrict__ y2, const float* __restrict__ stats,
                             const float* __restrict__ gamma, const float* __restrict__ beta,
                             float* __restrict__ out, int n)
{
    __shared__ float Rs[64 * 64];
    __shared__ float Xs[64 * XS_STRIDE];
    const int tid = threadIdx.x;
    const int rowBase = blockIdx.x * 64;

    for (int i = tid; i < 1024; i += 256)
        ((float4*)Rs)[i] = ((const float4*)R)[i];
    for (int i = tid; i < 1024; i += 256) {
        int r = i >> 4, c4 = i & 15;
        int row = rowBase + r;
        float4 v = make_float4(0.f, 0.f, 0.f, 0.f);
        if (row < n) v = ((const float4*)X)[row * 16 + c4];
        *(float4*)(Xs + r * XS_STRIDE + c4 * 4) = v;
    }
    __syncthreads();

    const int tx = tid & 15;
    const int ty = tid >> 4;
    float4 acc[4];
    #pragma unroll
    for (int r = 0; r < 4; r++) acc[r] = make_float4(0.f, 0.f, 0.f, 0.f);

    #pragma unroll 8
    for (int k = 0; k < 64; k++) {
        float a0 = Xs[(ty * 4 + 0) * XS_STRIDE + k];
        float a1 = Xs[(ty * 4 + 1) * XS_STRIDE + k];
        float a2 = Xs[(ty * 4 + 2) * XS_STRIDE + k];
        float a3 = Xs[(ty * 4 + 3) * XS_STRIDE + k];
        float4 b = ((const float4*)(Rs + k * 64))[tx];
        FMA4(acc[0], a0, b);
        FMA4(acc[1], a1, b);
        FMA4(acc[2], a2, b);
        FMA4(acc[3], a3, b);
    }

    float fn = 1.f / (float)n;
    float scale[4], shift[4];
    #pragma unroll
    for (int j = 0; j < 4; j++) {
        int c = tx * 4 + j;
        float mean = stats[c] * fn;
        float var  = stats[64 + c] * fn - mean * mean;
        float sc = gamma[c] * rsqrtf(var + 1e-3f);
        scale[j] = sc;
        shift[j] = beta[c] - mean * sc;
    }

    #pragma unroll
    for (int r = 0; r < 4; r++) {
        int row = rowBase + ty * 4 + r;
        if (row < n) {
            float4 yv = ((const float4*)(y2 + (size_t)row * 64))[tx];
            float o0 = acc[r].x + yv.x * scale[0] + shift[0];
            float o1 = acc[r].y + yv.y * scale[1] + shift[1];
            float o2 = acc[r].z + yv.z * scale[2] + shift[2];
            float o3 = acc[r].w + yv.w * scale[3] + shift[3];
            float4 ov;
            ov.x = o0 > 0.f ? o0 : 0.f;
            ov.y = o1 > 0.f ? o1 : 0.f;
            ov.z = o2 > 0.f ? o2 : 0.f;
            ov.w = o3 > 0.f ? o3 : 0.f;
            ((float4*)(out + (size_t)row * 64))[tx] = ov;
        }
    }
}

// ================= host =================
extern "C" void kernel_launch(void* const* d_in, const int* in_sizes, int n_in,
                              void* d_out, int out_size)
{
    const float* u   = (const float*)d_in[0];
    const float* v   = (const float*)d_in[1];
    const int*   es  = (const int*)  d_in[2];
    const int*   ee  = (const int*)  d_in[3];
    const float* Ui1 = (const float*)d_in[4];
    const float* Uj1 = (const float*)d_in[5];
    const float* Vi1 = (const float*)d_in[6];
    const float* Vj1 = (const float*)d_in[7];
    const float* bu1 = (const float*)d_in[8];
    const float* bv1 = (const float*)d_in[9];
    const float* Ui2 = (const float*)d_in[10];
    const float* Uj2 = (const float*)d_in[11];
    const float* Vi2 = (const float*)d_in[12];
    const float* Vj2 = (const float*)d_in[13];
    const float* bu2 = (const float*)d_in[14];
    const float* bv2 = (const float*)d_in[15];
    const float* R   = (const float*)d_in[16];
    const float* gamma1 = (const float*)d_in[17];
    const float* beta1  = (const float*)d_in[18];
    const float* gamma2 = (const float*)d_in[19];
    const float* beta2  = (const float*)d_in[20];

    const int nU = in_sizes[0] / 64;
    const int nV = in_sizes[1] / 64;
    const int n  = nU + nV;
    const int nE = in_sizes[2];

    float *px, *pxui, *pxvi, *pxvj, *py, *py2, *pst1, *pst2;
    int *pcnt;
    cudaGetSymbolAddress((void**)&px,   g_x);
    cudaGetSymbolAddress((void**)&pxui, g_xui);
    cudaGetSymbolAddress((void**)&pxvi, g_xvi);
    cudaGetSymbolAddress((void**)&pxvj, g_xvj);
    cudaGetSymbolAddress((void**)&py,   g_y);
    cudaGetSymbolAddress((void**)&py2,  g_y2);
    cudaGetSymbolAddress((void**)&pst1, g_stats1);
    cudaGetSymbolAddress((void**)&pst2, g_stats2);
    cudaGetSymbolAddress((void**)&pcnt, g_cnt);

    cudaFuncSetAttribute(gemm4_kernel<false>, cudaFuncAttributeMaxDynamicSharedMemorySize, GEMM4_SMEM);
    cudaFuncSetAttribute(gemm4_kernel<true>,  cudaFuncAttributeMaxDynamicSharedMemorySize, GEMM4_SMEM);

    // x_in = concat(u, v)
    cudaMemcpyAsync(px,                   u, (size_t)nU * 64 * sizeof(float), cudaMemcpyDeviceToDevice);
    cudaMemcpyAsync(px + (size_t)nU * 64, v, (size_t)nV * 64 * sizeof(float), cudaMemcpyDeviceToDevice);
    cudaMemsetAsync(pcnt, 0, (MAXN + 1) * sizeof(int));
    cudaMemsetAsync(pst1, 0, 2 * D * sizeof(float));
    cudaMemsetAsync(pst2, 0, 2 * D * sizeof(float));

    // ---- CSR build (dest-keyed) ----
    const int C = (n + NCHUNK - 1) / NCHUNK;
    const int eb = (nE + 255) / 256;
    hist_kernel<<<eb, 256>>>(ee, nE);
    scanA_kernel<<<NCHUNK / 256, 256>>>(n, C);
    scanB_kernel<<<1, NCHUNK>>>();
    scanC_kernel<<<NCHUNK / 256, 256>>>(n, C);
    scatter_kernel<<<eb, 256>>>(es, ee, nE);

    const int gemmBlocks = (n + 63) / 64;
    const int aggBlocks  = (n + 15) / 16;

    // ---- stage 1 ----
    gemm4_kernel<false><<<gemmBlocks, 256, GEMM4_SMEM>>>(px, Ui1, Uj1, Vi1, Vj1, bu1, bv1,
                                                         nullptr, nullptr, nullptr,
                                                         pxui, py, pxvi, pxvj, n);
    agg_kernel<<<aggBlocks, 256>>>(pxvi, pxvj, pxui, py, pst1, n);

    // ---- stage 2 (BN1+ReLU fused into X load) ----
    gemm4_kernel<true><<<gemmBlocks, 256, GEMM4_SMEM>>>(py, Ui2, Uj2, Vi2, Vj2, bu2, bv2,
                                                        pst1, gamma1, beta1,
                                                        pxui, py2, pxvi, pxvj, n);
    agg_kernel<<<aggBlocks, 256>>>(pxvi, pxvj, pxui, py2, pst2, n);

    // ---- final: relu(BN2(y2) + x_in @ R) ----
    final_kernel<<<gemmBlocks, 256>>>(px, R, py2, pst2, gamma2, beta2, (float*)d_out, n);
}

// round 3
// speedup vs baseline: 1.1213x; 1.0581x over previous
#include <cuda_runtime.h>
#include <math.h>

#define D 64
#define MAXN 100000
#define MAXE 1100000

// ---------------- static device scratch ----------------
__device__ float g_x  [MAXN * D];   // x_in = concat(u, v)
__device__ float g_xui[MAXN * D];
__device__ float g_xvi[MAXN * D];
__device__ float g_xvj[MAXN * D];   // includes +bv
__device__ float g_y  [MAXN * D];   // stage1 output
__device__ float g_y2 [MAXN * D];   // stage2 output
__device__ float g_stats1[2 * D];
__device__ float g_stats2[2 * D];
// CSR (edges sorted by destination)
__device__ int g_cnt[MAXN + 1];
__device__ int g_off[MAXN + 1];
__device__ int g_cur[MAXN];
__device__ int g_srcSorted[MAXE];
__device__ int g_bsum[512];

#define FMA4(ACC, A, B) do { (ACC).x += (A)*(B).x; (ACC).y += (A)*(B).y; \
                             (ACC).z += (A)*(B).z; (ACC).w += (A)*(B).w; } while(0)

// ================= CSR build =================
__global__ void hist_kernel(const int* __restrict__ ee, int nE)
{
    int e = blockIdx.x * blockDim.x + threadIdx.x;
    if (e < nE) atomicAdd(&g_cnt[ee[e]], 1);
}

// block-level inclusive scan of 256 counts -> exclusive into g_off, block total -> g_bsum
__global__ void scan_block_kernel(int n)
{
    __shared__ int sh[256];
    int tid = threadIdx.x;
    int i = blockIdx.x * 256 + tid;
    int v = (i < n) ? g_cnt[i] : 0;
    sh[tid] = v;
    __syncthreads();
    #pragma unroll
    for (int ofs = 1; ofs < 256; ofs <<= 1) {
        int x = (tid >= ofs) ? sh[tid - ofs] : 0;
        __syncthreads();
        sh[tid] += x;
        __syncthreads();
    }
    if (i <= n) g_off[i > n ? n : i] = sh[tid] - v;   // exclusive (guarded)
    if (i < n)  g_off[i] = sh[tid] - v;
    if (tid == 255) g_bsum[blockIdx.x] = sh[255];
}

// single-block exclusive scan of per-block totals (<=512)
__global__ void scan_tops_kernel(int nb)
{
    __shared__ int sh[512];
    int t = threadIdx.x;
    int v = (t < nb) ? g_bsum[t] : 0;
    sh[t] = v;
    __syncthreads();
    #pragma unroll
    for (int ofs = 1; ofs < 512; ofs <<= 1) {
        int x = (t >= ofs) ? sh[t - ofs] : 0;
        __syncthreads();
        sh[t] += x;
        __syncthreads();
    }
    g_bsum[t] = sh[t] - v;   // exclusive
}

__global__ void scan_add_kernel(int n)
{
    int i = blockIdx.x * 256 + threadIdx.x;
    if (i < n) {
        int o = g_off[i] + g_bsum[i >> 8];
        g_off[i] = o;
        g_cur[i] = o;
        if (i == n - 1) g_off[n] = o + g_cnt[i];
    }
}

__global__ void scatter_kernel(const int* __restrict__ es, const int* __restrict__ ee, int nE)
{
    int e = blockIdx.x * blockDim.x + threadIdx.x;
    if (e < nE) {
        int d = ee[e];
        int p = atomicAdd(&g_cur[d], 1);
        g_srcSorted[p] = es[e];
    }
}

// ================= fused 4-matrix GEMM: X @ [Ui|Uj|Vi|Vj] =================
#define XS_STRIDE 68
#define GEMM4_SMEM (64*256*4 + 64*XS_STRIDE*4)

template<bool BN>
__global__ void gemm4_kernel(const float* __restrict__ X,
                             const float* __restrict__ Ui, const float* __restrict__ Uj,
                             const float* __restrict__ Vi, const float* __restrict__ Vj,
                             const float* __restrict__ bu, const float* __restrict__ bv,
                             const float* __restrict__ stats, const float* __restrict__ gamma,
                             const float* __restrict__ beta,
                             float* __restrict__ xui, float* __restrict__ y,
                             float* __restrict__ xvi, float* __restrict__ xvj,
                             int n)
{
    extern __shared__ float smem[];
    float* Ws = smem;              // [64][256]
    float* Xs = smem + 64 * 256;   // [64][XS_STRIDE]
    __shared__ float s_scale[64], s_shift[64];
    const int tid = threadIdx.x;
    const int rowBase = blockIdx.x * 64;

    if (BN) {
        if (tid < 64) {
            float fn = 1.f / (float)n;
            float mean = stats[tid] * fn;
            float var  = stats[64 + tid] * fn - mean * mean;
            float sc = gamma[tid] * rsqrtf(var + 1e-3f);
            s_scale[tid] = sc;
            s_shift[tid] = beta[tid] - mean * sc;
        }
        __syncthreads();
    }

    {
        const float* mats[4] = {Ui, Uj, Vi, Vj};
        #pragma unroll
        for (int m = 0; m < 4; m++) {
            const float4* src = (const float4*)mats[m];
            for (int i = tid; i < 1024; i += 256) {
                int k = i >> 4, j4 = i & 15;
                ((float4*)(Ws + k * 256 + m * 64))[j4] = src[k * 16 + j4];
            }
        }
        for (int i = tid; i < 1024; i += 256) {
            int r = i >> 4, c4 = i & 15;
            int row = rowBase + r;
            float4 v = make_float4(0.f, 0.f, 0.f, 0.f);
            if (row < n) v = ((const float4*)X)[row * 16 + c4];
            if (BN) {
                int c = c4 * 4;
                v.x = fmaxf(v.x * s_scale[c+0] + s_shift[c+0], 0.f);
                v.y = fmaxf(v.y * s_scale[c+1] + s_shift[c+1], 0.f);
                v.z = fmaxf(v.z * s_scale[c+2] + s_shift[c+2], 0.f);
                v.w = fmaxf(v.w * s_scale[c+3] + s_shift[c+3], 0.f);
            }
            *(float4*)(Xs + r * XS_STRIDE + c4 * 4) = v;
        }
    }
    __syncthreads();

    const int tx = tid & 15;
    const int ty = tid >> 4;
    float4 acc[4][4];
    #pragma unroll
    for (int r = 0; r < 4; r++)
        #pragma unroll
        for (int c = 0; c < 4; c++) acc[r][c] = make_float4(0.f, 0.f, 0.f, 0.f);

    #pragma unroll 8
    for (int k = 0; k < 64; k++) {
        float a0 = Xs[(ty * 4 + 0) * XS_STRIDE + k];
        float a1 = Xs[(ty * 4 + 1) * XS_STRIDE + k];
        float a2 = Xs[(ty * 4 + 2) * XS_STRIDE + k];
        float a3 = Xs[(ty * 4 + 3) * XS_STRIDE + k];
        const float4* wrow = (const float4*)(Ws + k * 256);
        float4 b0 = wrow[tx * 4 + 0];
        float4 b1 = wrow[tx * 4 + 1];
        float4 b2 = wrow[tx * 4 + 2];
        float4 b3 = wrow[tx * 4 + 3];
        FMA4(acc[0][0], a0, b0); FMA4(acc[0][1], a0, b1); FMA4(acc[0][2], a0, b2); FMA4(acc[0][3], a0, b3);
        FMA4(acc[1][0], a1, b0); FMA4(acc[1][1], a1, b1); FMA4(acc[1][2], a1, b2); FMA4(acc[1][3], a1, b3);
        FMA4(acc[2][0], a2, b0); FMA4(acc[2][1], a2, b1); FMA4(acc[2][2], a2, b2); FMA4(acc[2][3], a2, b3);
        FMA4(acc[3][0], a3, b0); FMA4(acc[3][1], a3, b1); FMA4(acc[3][2], a3, b2); FMA4(acc[3][3], a3, b3);
    }

    const int m = tx >> 2;
    const int ccb = (tx & 3) * 16;
    float* dst; const float* bias;
    if      (m == 0) { dst = xui; bias = nullptr; }
    else if (m == 1) { dst = y;   bias = bu; }
    else if (m == 2) { dst = xvi; bias = nullptr; }
    else             { dst = xvj; bias = bv; }

    float4 bb[4];
    #pragma unroll
    for (int c = 0; c < 4; c++) {
        if (bias) bb[c] = ((const float4*)bias)[(ccb >> 2) + c];
        else      bb[c] = make_float4(0.f, 0.f, 0.f, 0.f);
    }

    #pragma unroll
    for (int r = 0; r < 4; r++) {
        int row = rowBase + ty * 4 + r;
        if (row < n) {
            float4* o = (float4*)(dst + row * 64 + ccb);
            #pragma unroll
            for (int c = 0; c < 4; c++) {
                float4 v = acc[r][c];
                v.x += bb[c].x; v.y += bb[c].y; v.z += bb[c].z; v.w += bb[c].w;
                o[c] = v;
            }
        }
    }
}

// ================= per-node aggregation (CSR, no atomics) + fused BN stats =================
// 16 threads per node, 16 nodes per 256-thread block, 4-edge unroll for MLP
__device__ __forceinline__ float4 sig_mul(float4 vi, float4 vj, float4 ui)
{
    float4 r;
    r.x = ui.x / (1.f + __expf(-(vi.x + vj.x)));
    r.y = ui.y / (1.f + __expf(-(vi.y + vj.y)));
    r.z = ui.z / (1.f + __expf(-(vi.z + vj.z)));
    r.w = ui.w / (1.f + __expf(-(vi.w + vj.w)));
    return r;
}

__global__ void agg_kernel(const float* __restrict__ xvi, const float* __restrict__ xvj,
                           const float* __restrict__ xui, float* __restrict__ y,
                           float* __restrict__ stats, int n)
{
    __shared__ float s_sum[64], s_sum2[64];
    const int tid = threadIdx.x;
    if (tid < 64) { s_sum[tid] = 0.f; s_sum2[tid] = 0.f; }
    __syncthreads();

    const int lane = tid & 15;
    const int grp  = tid >> 4;
    const int node = blockIdx.x * 16 + grp;

    if (node < n) {
        float4 vi  = ((const float4*)(xvi + (size_t)node * 64))[lane];
        float4 acc = ((const float4*)(y   + (size_t)node * 64))[lane];  // x@Uj + bu
        const int p1 = g_off[node + 1];
        int p = g_off[node];

        for (; p + 4 <= p1; p += 4) {
            int b0 = __ldg(g_srcSorted + p + 0);
            int b1 = __ldg(g_srcSorted + p + 1);
            int b2 = __ldg(g_srcSorted + p + 2);
            int b3 = __ldg(g_srcSorted + p + 3);
            float4 vj0 = __ldg((const float4*)(xvj + (size_t)b0 * 64) + lane);
            float4 ui0 = __ldg((const float4*)(xui + (size_t)b0 * 64) + lane);
            float4 vj1 = __ldg((const float4*)(xvj + (size_t)b1 * 64) + lane);
            float4 ui1 = __ldg((const float4*)(xui + (size_t)b1 * 64) + lane);
            float4 vj2 = __ldg((const float4*)(xvj + (size_t)b2 * 64) + lane);
            float4 ui2 = __ldg((const float4*)(xui + (size_t)b2 * 64) + lane);
            float4 vj3 = __ldg((const float4*)(xvj + (size_t)b3 * 64) + lane);
            float4 ui3 = __ldg((const float4*)(xui + (size_t)b3 * 64) + lane);
            float4 m0 = sig_mul(vi, vj0, ui0);
            float4 m1 = sig_mul(vi, vj1, ui1);
            float4 m2 = sig_mul(vi, vj2, ui2);
            float4 m3 = sig_mul(vi, vj3, ui3);
            acc.x += (m0.x + m1.x) + (m2.x + m3.x);
            acc.y += (m0.y + m1.y) + (m2.y + m3.y);
            acc.z += (m0.z + m1.z) + (m2.z + m3.z);
            acc.w += (m0.w + m1.w) + (m2.w + m3.w);
        }
        for (; p < p1; p++) {
            int b = __ldg(g_srcSorted + p);
            float4 vj = __ldg((const float4*)(xvj + (size_t)b * 64) + lane);
            float4 ui = __ldg((const float4*)(xui + (size_t)b * 64) + lane);
            float4 m = sig_mul(vi, vj, ui);
            acc.x += m.x; acc.y += m.y; acc.z += m.z; acc.w += m.w;
        }
        ((float4*)(y + (size_t)node * 64))[lane] = acc;

        int c = lane * 4;
        atomicAdd(&s_sum[c + 0], acc.x);  atomicAdd(&s_sum2[c + 0], acc.x * acc.x);
        atomicAdd(&s_sum[c + 1], acc.y);  atomicAdd(&s_sum2[c + 1], acc.y * acc.y);
        atomicAdd(&s_sum[c + 2], acc.z);  atomicAdd(&s_sum2[c + 2], acc.z * acc.z);
        atomicAdd(&s_sum[c + 3], acc.w);  atomicAdd(&s_sum2[c + 3], acc.w * acc.w);
    }
    __syncthreads();
    if (tid < 64) {
        atomicAdd(stats + tid,      s_sum[tid]);
        atomicAdd(stats + 64 + tid, s_sum2[tid]);
    }
}

// ================= final: out = relu( BN2(y2) + x_in @ R ) =================
__global__ void final_kernel(const float* __restrict__ X, const float* __restrict__ R,
                             const float* __restrict__ y2, const float* __restrict__ stats,
                             const float* __restrict__ gamma, const float* __restrict__ beta,
                             float* __restrict__ out, int n)
{
    __shared__ float Rs[64 * 64];
    __shared__ float Xs[64 * XS_STRIDE];
    const int tid = threadIdx.x;
    const int rowBase = blockIdx.x * 64;

    for (int i = tid; i < 1024; i += 256)
        ((float4*)Rs)[i] = ((const float4*)R)[i];
    for (int i = tid; i < 1024; i += 256) {
        int r = i >> 4, c4 = i & 15;
        int row = rowBase + r;
        float4 v = make_float4(0.f, 0.f, 0.f, 0.f);
        if (row < n) v = ((const float4*)X)[row * 16 + c4];
        *(float4*)(Xs + r * XS_STRIDE + c4 * 4) = v;
    }
    __syncthreads();

    const int tx = tid & 15;
    const int ty = tid >> 4;
    float4 acc[4];
    #pragma unroll
    for (int r = 0; r < 4; r++) acc[r] = make_float4(0.f, 0.f, 0.f, 0.f);

    #pragma unroll 8
    for (int k = 0; k < 64; k++) {
        float a0 = Xs[(ty * 4 + 0) * XS_STRIDE + k];
        float a1 = Xs[(ty * 4 + 1) * XS_STRIDE + k];
        float a2 = Xs[(ty * 4 + 2) * XS_STRIDE + k];
        float a3 = Xs[(ty * 4 + 3) * XS_STRIDE + k];
        float4 b = ((const float4*)(Rs + k * 64))[tx];
        FMA4(acc[0], a0, b);
        FMA4(acc[1], a1, b);
        FMA4(acc[2], a2, b);
        FMA4(acc[3], a3, b);
    }

    float fn = 1.f / (float)n;
    float scale[4], shift[4];
    #pragma unroll
    for (int j = 0; j < 4; j++) {
        int c = tx * 4 + j;
        float mean = stats[c] * fn;
        float var  = stats[64 + c] * fn - mean * mean;
        float sc = gamma[c] * rsqrtf(var + 1e-3f);
        scale[j] = sc;
        shift[j] = beta[c] - mean * sc;
    }

    #pragma unroll
    for (int r = 0; r < 4; r++) {
        int row = rowBase + ty * 4 + r;
        if (row < n) {
            float4 yv = ((const float4*)(y2 + (size_t)row * 64))[tx];
            float o0 = acc[r].x + yv.x * scale[0] + shift[0];
            float o1 = acc[r].y + yv.y * scale[1] + shift[1];
            float o2 = acc[r].z + yv.z * scale[2] + shift[2];
            float o3 = acc[r].w + yv.w * scale[3] + shift[3];
            float4 ov;
            ov.x = o0 > 0.f ? o0 : 0.f;
            ov.y = o1 > 0.f ? o1 : 0.f;
            ov.z = o2 > 0.f ? o2 : 0.f;
            ov.w = o3 > 0.f ? o3 : 0.f;
            ((float4*)(out + (size_t)row * 64))[tx] = ov;
        }
    }
}

// ================= host =================
extern "C" void kernel_launch(void* const* d_in, const int* in_sizes, int n_in,
                              void* d_out, int out_size)
{
    const float* u   = (const float*)d_in[0];
    const float* v   = (const float*)d_in[1];
    const int*   es  = (const int*)  d_in[2];
    const int*   ee  = (const int*)  d_in[3];
    const float* Ui1 = (const float*)d_in[4];
    const float* Uj1 = (const float*)d_in[5];
    const float* Vi1 = (const float*)d_in[6];
    const float* Vj1 = (const float*)d_in[7];
    const float* bu1 = (const float*)d_in[8];
    const float* bv1 = (const float*)d_in[9];
    const float* Ui2 = (const float*)d_in[10];
    const float* Uj2 = (const float*)d_in[11];
    const float* Vi2 = (const float*)d_in[12];
    const float* Vj2 = (const float*)d_in[13];
    const float* bu2 = (const float*)d_in[14];
    const float* bv2 = (const float*)d_in[15];
    const float* R   = (const float*)d_in[16];
    const float* gamma1 = (const float*)d_in[17];
    const float* beta1  = (const float*)d_in[18];
    const float* gamma2 = (const float*)d_in[19];
    const float* beta2  = (const float*)d_in[20];

    const int nU = in_sizes[0] / 64;
    const int nV = in_sizes[1] / 64;
    const int n  = nU + nV;
    const int nE = in_sizes[2];

    float *px, *pxui, *pxvi, *pxvj, *py, *py2, *pst1, *pst2;
    int *pcnt;
    cudaGetSymbolAddress((void**)&px,   g_x);
    cudaGetSymbolAddress((void**)&pxui, g_xui);
    cudaGetSymbolAddress((void**)&pxvi, g_xvi);
    cudaGetSymbolAddress((void**)&pxvj, g_xvj);
    cudaGetSymbolAddress((void**)&py,   g_y);
    cudaGetSymbolAddress((void**)&py2,  g_y2);
    cudaGetSymbolAddress((void**)&pst1, g_stats1);
    cudaGetSymbolAddress((void**)&pst2, g_stats2);
    cudaGetSymbolAddress((void**)&pcnt, g_cnt);

    cudaFuncSetAttribute(gemm4_kernel<false>, cudaFuncAttributeMaxDynamicSharedMemorySize, GEMM4_SMEM);
    cudaFuncSetAttribute(gemm4_kernel<true>,  cudaFuncAttributeMaxDynamicSharedMemorySize, GEMM4_SMEM);

    // x_in = concat(u, v)
    cudaMemcpyAsync(px,                   u, (size_t)nU * 64 * sizeof(float), cudaMemcpyDeviceToDevice);
    cudaMemcpyAsync(px + (size_t)nU * 64, v, (size_t)nV * 64 * sizeof(float), cudaMemcpyDeviceToDevice);
    cudaMemsetAsync(pcnt, 0, (MAXN + 1) * sizeof(int));
    cudaMemsetAsync(pst1, 0, 2 * D * sizeof(float));
    cudaMemsetAsync(pst2, 0, 2 * D * sizeof(float));

    // ---- CSR build (dest-keyed) ----
    const int eb = (nE + 255) / 256;
    const int nb = (n + 255) / 256;
    hist_kernel<<<eb, 256>>>(ee, nE);
    scan_block_kernel<<<nb, 256>>>(n);
    scan_tops_kernel<<<1, 512>>>(nb);
    scan_add_kernel<<<nb, 256>>>(n);
    scatter_kernel<<<eb, 256>>>(es, ee, nE);

    const int gemmBlocks = (n + 63) / 64;
    const int aggBlocks  = (n + 15) / 16;

    // ---- stage 1 ----
    gemm4_kernel<false><<<gemmBlocks, 256, GEMM4_SMEM>>>(px, Ui1, Uj1, Vi1, Vj1, bu1, bv1,
                                                         nullptr, nullptr, nullptr,
                                                         pxui, py, pxvi, pxvj, n);
    agg_kernel<<<aggBlocks, 256>>>(pxvi, pxvj, pxui, py, pst1, n);

    // ---- stage 2 (BN1+ReLU fused into X load) ----
    gemm4_kernel<true><<<gemmBlocks, 256, GEMM4_SMEM>>>(py, Ui2, Uj2, Vi2, Vj2, bu2, bv2,
                                                        pst1, gamma1, beta1,
                                                        pxui, py2, pxvi, pxvj, n);
    agg_kernel<<<aggBlocks, 256>>>(pxvi, pxvj, pxui, py2, pst2, n);

    // ---- final: relu(BN2(y2) + x_in @ R) ----
    final_kernel<<<gemmBlocks, 256>>>(px, R, py2, pst2, gamma2, beta2, (float*)d_out, n);
}